// round 2
// baseline (speedup 1.0000x reference)
#include <cuda_runtime.h>
#include <cstdint>

#define NN 100000
#define EE 1600000
#define FF 128
#define HH 4
#define LRELU_ALPHA 0.2f

// ---- device scratch (no allocations allowed) ----
__device__ float4 g_ssrc[NN];        // per-node src-scores, 4 heads
__device__ float4 g_sdst[NN];        // per-node dst-scores, 4 heads
__device__ int    g_cnt[NN];         // degree counts (zeroed each launch)
__device__ int    g_rowstart[NN + 1];
__device__ int    g_cursor[NN];
__device__ int    g_dstS[EE];        // CSR-ordered dst
__device__ float4 g_ecoef[EE];       // CSR-ordered 4-head edge coefficients

// K0: per-node scores, one warp per node. s_src[k] = sum_f x[f]*W[k][f]*a[k][f]
__global__ void k_scores(const float* __restrict__ x,
                         const float* __restrict__ W,
                         const float* __restrict__ a, int n) {
    __shared__ float wa_s[HH][FF];
    __shared__ float wa_d[HH][FF];
    int tid = threadIdx.x;
    for (int i = tid; i < HH * FF; i += blockDim.x) {
        int k = i / FF, f = i % FF;
        float w = W[k * FF + f];
        wa_s[k][f] = w * a[k * 2 * FF + f];
        wa_d[k][f] = w * a[k * 2 * FF + FF + f];
    }
    __syncthreads();
    int lane = tid & 31, warp = tid >> 5;
    int node = blockIdx.x * (blockDim.x >> 5) + warp;
    if (node >= n) return;
    const float* xr = x + (size_t)node * FF;
    float ss[HH] = {0.f, 0.f, 0.f, 0.f};
    float sd[HH] = {0.f, 0.f, 0.f, 0.f};
#pragma unroll
    for (int c = 0; c < 4; c++) {
        int f = lane + c * 32;
        float xv = xr[f];
#pragma unroll
        for (int k = 0; k < HH; k++) {
            ss[k] = fmaf(xv, wa_s[k][f], ss[k]);
            sd[k] = fmaf(xv, wa_d[k][f], sd[k]);
        }
    }
#pragma unroll
    for (int k = 0; k < HH; k++) {
#pragma unroll
        for (int o = 16; o > 0; o >>= 1) {
            ss[k] += __shfl_down_sync(0xFFFFFFFFu, ss[k], o);
            sd[k] += __shfl_down_sync(0xFFFFFFFFu, sd[k], o);
        }
    }
    if (lane == 0) {
        g_ssrc[node] = make_float4(ss[0], ss[1], ss[2], ss[3]);
        g_sdst[node] = make_float4(sd[0], sd[1], sd[2], sd[3]);
    }
}

__global__ void k_zero(int n) {
    int i = blockIdx.x * blockDim.x + threadIdx.x;
    if (i < n) g_cnt[i] = 0;
}

__global__ void k_count(const int* __restrict__ src, int e) {
    int i = blockIdx.x * blockDim.x + threadIdx.x;
    if (i < e) atomicAdd(&g_cnt[src[i]], 1);
}

// K3: single-block exclusive scan over g_cnt -> g_rowstart, g_cursor
__global__ void k_scan(int n) {
    __shared__ int warp_sums[32];
    __shared__ int carry_s;
    int tid = threadIdx.x, lane = tid & 31, w = tid >> 5;
    if (tid == 0) carry_s = 0;
    __syncthreads();
    for (int base = 0; base < n; base += 1024) {
        int i = base + tid;
        int v = (i < n) ? g_cnt[i] : 0;
        int s = v;
#pragma unroll
        for (int o = 1; o < 32; o <<= 1) {
            int t = __shfl_up_sync(0xFFFFFFFFu, s, o);
            if (lane >= o) s += t;
        }
        if (lane == 31) warp_sums[w] = s;
        __syncthreads();
        if (w == 0) {
            int ws = warp_sums[lane];
#pragma unroll
            for (int o = 1; o < 32; o <<= 1) {
                int t = __shfl_up_sync(0xFFFFFFFFu, ws, o);
                if (lane >= o) ws += t;
            }
            warp_sums[lane] = ws;
        }
        __syncthreads();
        int prev = (w > 0) ? warp_sums[w - 1] : 0;
        int excl = carry_s + prev + s - v;
        if (i < n) { g_rowstart[i] = excl; g_cursor[i] = excl; }
        int total = warp_sums[31];
        __syncthreads();
        if (tid == 0) carry_s += total;
        __syncthreads();
    }
    if (threadIdx.x == 0) g_rowstart[n] = carry_s;
}

// K4: per edge: 4-head coefficient, scatter into CSR slot
__global__ void k_fill(const int* __restrict__ src, const int* __restrict__ dst,
                       const float* __restrict__ adj, int e) {
    int i = blockIdx.x * blockDim.x + threadIdx.x;
    if (i >= e) return;
    int s = src[i], d = dst[i];
    float av = adj[i];
    float4 a4 = g_ssrc[s];
    float4 b4 = g_sdst[d];
    float z0 = a4.x + b4.x, z1 = a4.y + b4.y, z2 = a4.z + b4.z, z3 = a4.w + b4.w;
    z0 = z0 > 0.f ? z0 : LRELU_ALPHA * z0;
    z1 = z1 > 0.f ? z1 : LRELU_ALPHA * z1;
    z2 = z2 > 0.f ? z2 : LRELU_ALPHA * z2;
    z3 = z3 > 0.f ? z3 : LRELU_ALPHA * z3;
    float4 ec = make_float4(expf(z0) * av, expf(z1) * av, expf(z2) * av, expf(z3) * av);
    int slot = atomicAdd(&g_cursor[s], 1);
    g_dstS[slot] = d;
    g_ecoef[slot] = ec;
}

// K5: warp per output node, float4 gather of x[dst]; epilogue W*acc/rowsum, ELU, mean
__global__ void k_agg(const float* __restrict__ x, const float* __restrict__ W,
                      float* __restrict__ out, int n) {
    int lane = threadIdx.x & 31, warp = threadIdx.x >> 5;
    int node = blockIdx.x * (blockDim.x >> 5) + warp;
    if (node >= n) return;
    int beg = g_rowstart[node];
    int end = g_rowstart[node + 1];
    float acc[HH][4];
#pragma unroll
    for (int k = 0; k < HH; k++)
#pragma unroll
        for (int c = 0; c < 4; c++) acc[k][c] = 0.f;
    float rs[HH] = {0.f, 0.f, 0.f, 0.f};
    for (int j = beg; j < end; j++) {
        int d = g_dstS[j];
        float4 ec = g_ecoef[j];
        float4 xv = ((const float4*)(x + (size_t)d * FF))[lane];
        acc[0][0] = fmaf(ec.x, xv.x, acc[0][0]);
        acc[0][1] = fmaf(ec.x, xv.y, acc[0][1]);
        acc[0][2] = fmaf(ec.x, xv.z, acc[0][2]);
        acc[0][3] = fmaf(ec.x, xv.w, acc[0][3]);
        acc[1][0] = fmaf(ec.y, xv.x, acc[1][0]);
        acc[1][1] = fmaf(ec.y, xv.y, acc[1][1]);
        acc[1][2] = fmaf(ec.y, xv.z, acc[1][2]);
        acc[1][3] = fmaf(ec.y, xv.w, acc[1][3]);
        acc[2][0] = fmaf(ec.z, xv.x, acc[2][0]);
        acc[2][1] = fmaf(ec.z, xv.y, acc[2][1]);
        acc[2][2] = fmaf(ec.z, xv.z, acc[2][2]);
        acc[2][3] = fmaf(ec.z, xv.w, acc[2][3]);
        acc[3][0] = fmaf(ec.w, xv.x, acc[3][0]);
        acc[3][1] = fmaf(ec.w, xv.y, acc[3][1]);
        acc[3][2] = fmaf(ec.w, xv.z, acc[3][2]);
        acc[3][3] = fmaf(ec.w, xv.w, acc[3][3]);
        rs[0] += ec.x; rs[1] += ec.y; rs[2] += ec.z; rs[3] += ec.w;
    }
    float inv[HH];
#pragma unroll
    for (int k = 0; k < HH; k++) inv[k] = 1.f / rs[k];
    float o[4] = {0.f, 0.f, 0.f, 0.f};
#pragma unroll
    for (int k = 0; k < HH; k++) {
        float4 w4 = ((const float4*)(W + k * FF))[lane];
        float v0 = acc[k][0] * w4.x * inv[k];
        float v1 = acc[k][1] * w4.y * inv[k];
        float v2 = acc[k][2] * w4.z * inv[k];
        float v3 = acc[k][3] * w4.w * inv[k];
        o[0] += v0 > 0.f ? v0 : expm1f(v0);
        o[1] += v1 > 0.f ? v1 : expm1f(v1);
        o[2] += v2 > 0.f ? v2 : expm1f(v2);
        o[3] += v3 > 0.f ? v3 : expm1f(v3);
    }
    float4 res = make_float4(o[0] * 0.25f, o[1] * 0.25f, o[2] * 0.25f, o[3] * 0.25f);
    ((float4*)(out + (size_t)node * FF))[lane] = res;
}

extern "C" void kernel_launch(void* const* d_in, const int* in_sizes, int n_in,
                              void* d_out, int out_size) {
    const float* x   = (const float*)d_in[0];   // [N, F]
    const int*   edge = (const int*)d_in[1];    // [2, E]
    const float* adj = (const float*)d_in[2];   // [E]
    const float* W   = (const float*)d_in[3];   // [H, F]
    const float* a   = (const float*)d_in[4];   // [H, 2F]
    float* out = (float*)d_out;

    int n = in_sizes[0] / FF;
    int e = in_sizes[2];
    const int* src = edge;
    const int* dst = edge + e;

    k_scores<<<(n + 3) / 4, 128>>>(x, W, a, n);
    k_zero<<<(n + 255) / 256, 256>>>(n);
    k_count<<<(e + 255) / 256, 256>>>(src, e);
    k_scan<<<1, 1024>>>(n);
    k_fill<<<(e + 255) / 256, 256>>>(src, dst, adj, e);
    k_agg<<<(n + 3) / 4, 128>>>(x, W, out, n);
}

// round 4
// speedup vs baseline: 1.3068x; 1.3068x over previous
#include <cuda_runtime.h>
#include <cstdint>

#define NN 100000
#define EE 1600000
#define FF 128
#define HH 4
#define LRELU_ALPHA 0.2f
#define SCAN_B 1024
#define MAX_BLOCKS 128

// ---- device scratch (no allocations allowed) ----
__device__ float4 g_ssrc[NN];        // per-node src-scores, 4 heads
__device__ float4 g_sdst[NN];        // per-node dst-scores, 4 heads
__device__ int    g_cnt[NN];         // degree counts
__device__ int    g_rowstart[NN + 1];
__device__ int    g_cursor[NN];
__device__ int    g_blocksum[MAX_BLOCKS];
__device__ int    g_dstS[EE];        // CSR-ordered dst
__device__ float4 g_ecoef[EE];       // CSR-ordered 4-head edge coefficients

// K0: per-node scores, one warp per node; also zeroes g_cnt (ordering: k_count
// launches after this kernel completes on the same stream).
__global__ void k_scores(const float* __restrict__ x,
                         const float* __restrict__ W,
                         const float* __restrict__ a, int n) {
    __shared__ float wa_s[HH][FF];
    __shared__ float wa_d[HH][FF];
    int tid = threadIdx.x;
    for (int i = tid; i < HH * FF; i += blockDim.x) {
        int k = i / FF, f = i % FF;
        float w = W[k * FF + f];
        wa_s[k][f] = w * a[k * 2 * FF + f];
        wa_d[k][f] = w * a[k * 2 * FF + FF + f];
    }
    __syncthreads();
    int lane = tid & 31, warp = tid >> 5;
    int node = blockIdx.x * (blockDim.x >> 5) + warp;
    if (node >= n) return;
    if (lane == 16) g_cnt[node] = 0;
    const float* xr = x + (size_t)node * FF;
    float ss[HH] = {0.f, 0.f, 0.f, 0.f};
    float sd[HH] = {0.f, 0.f, 0.f, 0.f};
#pragma unroll
    for (int c = 0; c < 4; c++) {
        int f = lane + c * 32;
        float xv = xr[f];
#pragma unroll
        for (int k = 0; k < HH; k++) {
            ss[k] = fmaf(xv, wa_s[k][f], ss[k]);
            sd[k] = fmaf(xv, wa_d[k][f], sd[k]);
        }
    }
#pragma unroll
    for (int k = 0; k < HH; k++) {
#pragma unroll
        for (int o = 16; o > 0; o >>= 1) {
            ss[k] += __shfl_down_sync(0xFFFFFFFFu, ss[k], o);
            sd[k] += __shfl_down_sync(0xFFFFFFFFu, sd[k], o);
        }
    }
    if (lane == 0) {
        g_ssrc[node] = make_float4(ss[0], ss[1], ss[2], ss[3]);
        g_sdst[node] = make_float4(sd[0], sd[1], sd[2], sd[3]);
    }
}

__global__ void k_count(const int* __restrict__ src, int e) {
    int i = blockIdx.x * blockDim.x + threadIdx.x;
    if (i < e) atomicAdd(&g_cnt[src[i]], 1);
}

// Phase 1: per-block exclusive scan of g_cnt chunk -> g_rowstart (chunk-local),
// block total -> g_blocksum[bid]
__global__ void k_scan_local(int n) {
    __shared__ int warp_sums[32];
    int tid = threadIdx.x, lane = tid & 31, w = tid >> 5;
    int i = blockIdx.x * SCAN_B + tid;
    int v = (i < n) ? g_cnt[i] : 0;
    int s = v;
#pragma unroll
    for (int o = 1; o < 32; o <<= 1) {
        int t = __shfl_up_sync(0xFFFFFFFFu, s, o);
        if (lane >= o) s += t;
    }
    if (lane == 31) warp_sums[w] = s;
    __syncthreads();
    if (w == 0) {
        int ws = warp_sums[lane];
#pragma unroll
        for (int o = 1; o < 32; o <<= 1) {
            int t = __shfl_up_sync(0xFFFFFFFFu, ws, o);
            if (lane >= o) ws += t;
        }
        warp_sums[lane] = ws;
    }
    __syncthreads();
    int excl = (w > 0 ? warp_sums[w - 1] : 0) + s - v;
    if (i < n) g_rowstart[i] = excl;
    if (tid == 0) g_blocksum[blockIdx.x] = warp_sums[31];
}

// Phase 2: single small block exclusive-scans the <=128 block sums in place
__global__ void k_scan_blocks(int nb) {
    __shared__ int warp_sums[4];
    int tid = threadIdx.x, lane = tid & 31, w = tid >> 5;
    int v = (tid < nb) ? g_blocksum[tid] : 0;
    int s = v;
#pragma unroll
    for (int o = 1; o < 32; o <<= 1) {
        int t = __shfl_up_sync(0xFFFFFFFFu, s, o);
        if (lane >= o) s += t;
    }
    if (lane == 31) warp_sums[w] = s;
    __syncthreads();
    int carry = 0;
#pragma unroll
    for (int j = 0; j < 4; j++) if (j < w) carry += warp_sums[j];
    if (tid < nb) g_blocksum[tid] = carry + s - v;
}

// Phase 3: add block offsets; init cursor; write rowstart[n] = e
__global__ void k_scan_add(int n, int e) {
    int i = blockIdx.x * SCAN_B + threadIdx.x;
    if (i < n) {
        int val = g_rowstart[i] + g_blocksum[blockIdx.x];
        g_rowstart[i] = val;
        g_cursor[i] = val;
    }
    if (i == 0) g_rowstart[n] = e;
}

// K4: per edge: 4-head coefficient, scatter into CSR slot
__global__ void k_fill(const int* __restrict__ src, const int* __restrict__ dst,
                       const float* __restrict__ adj, int e) {
    int i = blockIdx.x * blockDim.x + threadIdx.x;
    if (i >= e) return;
    int s = src[i], d = dst[i];
    float av = adj[i];
    float4 a4 = g_ssrc[s];
    float4 b4 = g_sdst[d];
    float z0 = a4.x + b4.x, z1 = a4.y + b4.y, z2 = a4.z + b4.z, z3 = a4.w + b4.w;
    z0 = z0 > 0.f ? z0 : LRELU_ALPHA * z0;
    z1 = z1 > 0.f ? z1 : LRELU_ALPHA * z1;
    z2 = z2 > 0.f ? z2 : LRELU_ALPHA * z2;
    z3 = z3 > 0.f ? z3 : LRELU_ALPHA * z3;
    float4 ec = make_float4(expf(z0) * av, expf(z1) * av, expf(z2) * av, expf(z3) * av);
    int slot = atomicAdd(&g_cursor[s], 1);
    g_dstS[slot] = d;
    g_ecoef[slot] = ec;
}

// K5: warp per output node, float4 gather of x[dst]; epilogue W*acc/rowsum, ELU, mean
__global__ void k_agg(const float* __restrict__ x, const float* __restrict__ W,
                      float* __restrict__ out, int n) {
    int lane = threadIdx.x & 31, warp = threadIdx.x >> 5;
    int node = blockIdx.x * (blockDim.x >> 5) + warp;
    if (node >= n) return;
    int beg = g_rowstart[node];
    int end = g_rowstart[node + 1];
    float acc[HH][4];
#pragma unroll
    for (int k = 0; k < HH; k++)
#pragma unroll
        for (int c = 0; c < 4; c++) acc[k][c] = 0.f;
    float rs[HH] = {0.f, 0.f, 0.f, 0.f};
    for (int j = beg; j < end; j++) {
        int d = g_dstS[j];
        float4 ec = g_ecoef[j];
        float4 xv = ((const float4*)(x + (size_t)d * FF))[lane];
        acc[0][0] = fmaf(ec.x, xv.x, acc[0][0]);
        acc[0][1] = fmaf(ec.x, xv.y, acc[0][1]);
        acc[0][2] = fmaf(ec.x, xv.z, acc[0][2]);
        acc[0][3] = fmaf(ec.x, xv.w, acc[0][3]);
        acc[1][0] = fmaf(ec.y, xv.x, acc[1][0]);
        acc[1][1] = fmaf(ec.y, xv.y, acc[1][1]);
        acc[1][2] = fmaf(ec.y, xv.z, acc[1][2]);
        acc[1][3] = fmaf(ec.y, xv.w, acc[1][3]);
        acc[2][0] = fmaf(ec.z, xv.x, acc[2][0]);
        acc[2][1] = fmaf(ec.z, xv.y, acc[2][1]);
        acc[2][2] = fmaf(ec.z, xv.z, acc[2][2]);
        acc[2][3] = fmaf(ec.z, xv.w, acc[2][3]);
        acc[3][0] = fmaf(ec.w, xv.x, acc[3][0]);
        acc[3][1] = fmaf(ec.w, xv.y, acc[3][1]);
        acc[3][2] = fmaf(ec.w, xv.z, acc[3][2]);
        acc[3][3] = fmaf(ec.w, xv.w, acc[3][3]);
        rs[0] += ec.x; rs[1] += ec.y; rs[2] += ec.z; rs[3] += ec.w;
    }
    float inv[HH];
#pragma unroll
    for (int k = 0; k < HH; k++) inv[k] = 1.f / rs[k];
    float o[4] = {0.f, 0.f, 0.f, 0.f};
#pragma unroll
    for (int k = 0; k < HH; k++) {
        float4 w4 = ((const float4*)(W + k * FF))[lane];
        float v0 = acc[k][0] * w4.x * inv[k];
        float v1 = acc[k][1] * w4.y * inv[k];
        float v2 = acc[k][2] * w4.z * inv[k];
        float v3 = acc[k][3] * w4.w * inv[k];
        o[0] += v0 > 0.f ? v0 : expm1f(v0);
        o[1] += v1 > 0.f ? v1 : expm1f(v1);
        o[2] += v2 > 0.f ? v2 : expm1f(v2);
        o[3] += v3 > 0.f ? v3 : expm1f(v3);
    }
    float4 res = make_float4(o[0] * 0.25f, o[1] * 0.25f, o[2] * 0.25f, o[3] * 0.25f);
    ((float4*)(out + (size_t)node * FF))[lane] = res;
}

extern "C" void kernel_launch(void* const* d_in, const int* in_sizes, int n_in,
                              void* d_out, int out_size) {
    const float* x   = (const float*)d_in[0];   // [N, F]
    const int*   edge = (const int*)d_in[1];    // [2, E]
    const float* adj = (const float*)d_in[2];   // [E]
    const float* W   = (const float*)d_in[3];   // [H, F]
    const float* a   = (const float*)d_in[4];   // [H, 2F]
    float* out = (float*)d_out;

    int n = in_sizes[0] / FF;
    int e = in_sizes[2];
    const int* src = edge;
    const int* dst = edge + e;

    int nb = (n + SCAN_B - 1) / SCAN_B;   // <= 128 for N=100k

    k_scores<<<(n + 3) / 4, 128>>>(x, W, a, n);
    k_count<<<(e + 255) / 256, 256>>>(src, e);
    k_scan_local<<<nb, SCAN_B>>>(n);
    k_scan_blocks<<<1, 128>>>(nb);
    k_scan_add<<<nb, SCAN_B>>>(n, e);
    k_fill<<<(e + 255) / 256, 256>>>(src, dst, adj, e);
    k_agg<<<(n + 3) / 4, 128>>>(x, W, out, n);
}